// round 1
// baseline (speedup 1.0000x reference)
#include <cuda_runtime.h>
#include <math_constants.h>

#define NN   100000
#define EE   3200000
#define FIN  512
#define HID  16
#define NG   10
#define GF   160   // NG*HID
#define LAMDA 0.001f
#define EPSN  1e-5f

// ---------------- device scratch (no allocations allowed) ----------------
__device__ float  g_deg[NN];          // deg, then dinv in place
__device__ float  g_h  [NN * HID];    // mm output
__device__ float  g_agg[NN * HID];    // scatter output
__device__ float  g_x  [NN * HID];    // post-layer features
__device__ float  g_s  [NN * NG];     // softmax cluster assignments
__device__ double g_sums[2 * GF];     // batch-stat accumulators
__device__ float  g_rsg[GF];          // rsqrt(var+eps)*gamma
__device__ float  g_cvec[HID];        // per-feature constant term

// ---------------- degree / norm ----------------
__global__ void zero_deg_kernel() {
    int i = blockIdx.x * blockDim.x + threadIdx.x;
    if (i < NN) g_deg[i] = 0.0f;
}

__global__ void count_deg_kernel(const int* __restrict__ ei) {
    int e = blockIdx.x * blockDim.x + threadIdx.x;
    if (e < EE) atomicAdd(&g_deg[__ldg(&ei[EE + e])], 1.0f);
}

__global__ void dinv_kernel() {
    int i = blockIdx.x * blockDim.x + threadIdx.x;
    if (i < NN) {
        float d = g_deg[i];
        g_deg[i] = (d > 0.0f) ? rsqrtf(d) : 0.0f;
    }
}

// ---------------- zero agg + stat sums ----------------
__global__ void zero_agg_kernel() {
    int i = blockIdx.x * blockDim.x + threadIdx.x;
    if (i < NN * HID) g_agg[i] = 0.0f;
    if (i < 2 * GF)  g_sums[i] = 0.0;
}

// ---------------- mm0: [N,512] @ [512,16] -> g_h ----------------
// 4 nodes per thread, W resident in smem, register-tiled.
__global__ __launch_bounds__(128) void mm0_kernel(const float* __restrict__ x,
                                                  const float* __restrict__ W) {
    __shared__ float Ws[FIN * HID];
    for (int i = threadIdx.x; i < FIN * HID; i += 128) Ws[i] = W[i];
    __syncthreads();

    int base = blockIdx.x * 512 + threadIdx.x;
    int n[4], nc[4];
#pragma unroll
    for (int t = 0; t < 4; t++) {
        n[t]  = base + t * 128;
        nc[t] = n[t] < NN ? n[t] : NN - 1;
    }

    float acc[4][HID];
#pragma unroll
    for (int t = 0; t < 4; t++)
#pragma unroll
        for (int f = 0; f < HID; f++) acc[t][f] = 0.0f;

    const float4* x4 = (const float4*)x;
    for (int k4 = 0; k4 < FIN / 4; k4++) {
        float xk[4][4];
#pragma unroll
        for (int t = 0; t < 4; t++) {
            float4 v = x4[(size_t)nc[t] * (FIN / 4) + k4];
            xk[t][0] = v.x; xk[t][1] = v.y; xk[t][2] = v.z; xk[t][3] = v.w;
        }
#pragma unroll
        for (int kk = 0; kk < 4; kk++) {
#pragma unroll
            for (int f = 0; f < HID; f++) {
                float w = Ws[(k4 * 4 + kk) * HID + f];
#pragma unroll
                for (int t = 0; t < 4; t++) acc[t][f] += xk[t][kk] * w;
            }
        }
    }

#pragma unroll
    for (int t = 0; t < 4; t++) {
        if (n[t] < NN) {
            float4* o = (float4*)&g_h[(size_t)n[t] * HID];
#pragma unroll
            for (int q = 0; q < 4; q++)
                o[q] = make_float4(acc[t][q * 4 + 0], acc[t][q * 4 + 1],
                                   acc[t][q * 4 + 2], acc[t][q * 4 + 3]);
        }
    }
}

// ---------------- mm16: [N,16] @ [16,16] -> g_h ----------------
__global__ void mm16_kernel(const float* __restrict__ xin,
                            const float* __restrict__ W) {
    __shared__ float Ws[HID * HID];
    if (threadIdx.x < HID * HID) Ws[threadIdx.x] = W[threadIdx.x];
    __syncthreads();
    int nIdx = blockIdx.x * blockDim.x + threadIdx.x;
    if (nIdx >= NN) return;

    float xr[HID];
    const float4* xi = (const float4*)&xin[(size_t)nIdx * HID];
#pragma unroll
    for (int q = 0; q < 4; q++) {
        float4 v = xi[q];
        xr[q * 4 + 0] = v.x; xr[q * 4 + 1] = v.y; xr[q * 4 + 2] = v.z; xr[q * 4 + 3] = v.w;
    }
    float acc[HID];
#pragma unroll
    for (int f = 0; f < HID; f++) acc[f] = 0.0f;
#pragma unroll
    for (int k = 0; k < HID; k++)
#pragma unroll
        for (int f = 0; f < HID; f++) acc[f] += xr[k] * Ws[k * HID + f];

    float4* o = (float4*)&g_h[(size_t)nIdx * HID];
#pragma unroll
    for (int q = 0; q < 4; q++)
        o[q] = make_float4(acc[q * 4 + 0], acc[q * 4 + 1], acc[q * 4 + 2], acc[q * 4 + 3]);
}

// ---------------- scatter: agg[col] += norm * h[row], 4 threads/edge ----------------
__global__ void scatter_kernel(const int* __restrict__ ei) {
    unsigned gt = blockIdx.x * blockDim.x + threadIdx.x;
    if (gt >= (unsigned)EE * 4u) return;
    int e = gt >> 2;
    int p = gt & 3;
    int r = __ldg(&ei[e]);
    int c = __ldg(&ei[EE + e]);
    float nrm = g_deg[r] * g_deg[c];
    float4 v = ((const float4*)g_h)[(size_t)r * 4 + p];
    v.x *= nrm; v.y *= nrm; v.z *= nrm; v.w *= nrm;
    float* dst = &g_agg[(size_t)c * HID + p * 4];
    asm volatile("red.global.add.v4.f32 [%0], {%1,%2,%3,%4};"
                 :: "l"(dst), "f"(v.x), "f"(v.y), "f"(v.z), "f"(v.w)
                 : "memory");
}

// ---------------- stats: softmax + per-channel sums ----------------
__global__ void stats_kernel(const float* __restrict__ L) {
    __shared__ float Ls[HID * NG];
    __shared__ float xs[256 * HID];
    __shared__ float ss[256 * NG];
    int tid = threadIdx.x;
    if (tid < HID * NG) Ls[tid] = L[tid];
    __syncthreads();

    int nIdx = blockIdx.x * 256 + tid;
    float xr[HID];
    float sv[NG];
#pragma unroll
    for (int k = 0; k < HID; k++) xr[k] = 0.0f;
#pragma unroll
    for (int g = 0; g < NG; g++) sv[g] = 0.0f;

    if (nIdx < NN) {
        const float4* xi = (const float4*)&g_agg[(size_t)nIdx * HID];
#pragma unroll
        for (int q = 0; q < 4; q++) {
            float4 v = xi[q];
            xr[q * 4 + 0] = v.x; xr[q * 4 + 1] = v.y; xr[q * 4 + 2] = v.z; xr[q * 4 + 3] = v.w;
        }
        float logit[NG];
#pragma unroll
        for (int g = 0; g < NG; g++) logit[g] = 0.0f;
#pragma unroll
        for (int k = 0; k < HID; k++)
#pragma unroll
            for (int g = 0; g < NG; g++) logit[g] += xr[k] * Ls[k * NG + g];
        float m = -CUDART_INF_F;
#pragma unroll
        for (int g = 0; g < NG; g++) m = fmaxf(m, logit[g]);
        float sum = 0.0f;
#pragma unroll
        for (int g = 0; g < NG; g++) { sv[g] = __expf(logit[g] - m); sum += sv[g]; }
        float inv = 1.0f / sum;
#pragma unroll
        for (int g = 0; g < NG; g++) sv[g] *= inv;
#pragma unroll
        for (int g = 0; g < NG; g++) g_s[(size_t)nIdx * NG + g] = sv[g];
    }

    {
        float4* xw = (float4*)&xs[tid * HID];
#pragma unroll
        for (int q = 0; q < 4; q++)
            xw[q] = make_float4(xr[q * 4 + 0], xr[q * 4 + 1], xr[q * 4 + 2], xr[q * 4 + 3]);
#pragma unroll
        for (int g = 0; g < NG; g++) ss[tid * NG + g] = sv[g];
    }
    __syncthreads();

    if (tid < GF) {
        int g = tid >> 4;
        int f = tid & 15;
        float a1 = 0.0f, a2 = 0.0f;
        for (int j = 0; j < 256; j++) {
            float t = ss[j * NG + g] * xs[j * HID + f];
            a1 += t;
            a2 += t * t;
        }
        atomicAdd(&g_sums[tid], (double)a1);
        atomicAdd(&g_sums[GF + tid], (double)a2);
    }
}

// ---------------- finalize batch-norm constants ----------------
__global__ void finalize_kernel(const float* __restrict__ gamma,
                                const float* __restrict__ beta) {
    __shared__ float tsh[GF];
    int c = threadIdx.x;
    if (c < GF) {
        double mean = g_sums[c] / (double)NN;
        double var  = g_sums[GF + c] / (double)NN - mean * mean;
        float v = (float)var;
        if (v < 0.0f) v = 0.0f;
        float rs = rsqrtf(v + EPSN);
        float rg = rs * gamma[c];
        g_rsg[c] = rg;
        tsh[c] = beta[c] - (float)mean * rg;
    }
    __syncthreads();
    if (c < HID) {
        float cf = 0.0f;
#pragma unroll
        for (int g = 0; g < NG; g++) cf += tsh[g * HID + c];
        g_cvec[c] = cf;
    }
}

// ---------------- apply: x + lambda*(x*a + c), relu ----------------
__global__ void apply_kernel(float* __restrict__ out) {
    __shared__ float rg[GF];
    __shared__ float cs[HID];
    int tid = threadIdx.x;
    if (tid < GF) rg[tid] = g_rsg[tid];
    if (tid < HID) cs[tid] = g_cvec[tid];
    __syncthreads();

    int nIdx = blockIdx.x * 256 + tid;
    if (nIdx >= NN) return;

    float sv[NG];
#pragma unroll
    for (int g = 0; g < NG; g++) sv[g] = g_s[(size_t)nIdx * NG + g];

    float xr[HID];
    const float4* xi = (const float4*)&g_agg[(size_t)nIdx * HID];
#pragma unroll
    for (int q = 0; q < 4; q++) {
        float4 v = xi[q];
        xr[q * 4 + 0] = v.x; xr[q * 4 + 1] = v.y; xr[q * 4 + 2] = v.z; xr[q * 4 + 3] = v.w;
    }

    float res[HID];
#pragma unroll
    for (int f = 0; f < HID; f++) {
        float a = 0.0f;
#pragma unroll
        for (int g = 0; g < NG; g++) a += sv[g] * rg[g * HID + f];
        float v = xr[f] + LAMDA * (xr[f] * a + cs[f]);
        res[f] = fmaxf(v, 0.0f);
    }

    float4* o = (float4*)&out[(size_t)nIdx * HID];
#pragma unroll
    for (int q = 0; q < 4; q++)
        o[q] = make_float4(res[q * 4 + 0], res[q * 4 + 1], res[q * 4 + 2], res[q * 4 + 3]);
}

// ---------------- launcher ----------------
extern "C" void kernel_launch(void* const* d_in, const int* in_sizes, int n_in,
                              void* d_out, int out_size) {
    const float* x  = (const float*)d_in[0];
    const int*   ei = (const int*)d_in[1];
    const float* W[3] = {(const float*)d_in[2], (const float*)d_in[3], (const float*)d_in[4]};
    const float* L[3] = {(const float*)d_in[5], (const float*)d_in[6], (const float*)d_in[7]};
    const float* gm[3] = {(const float*)d_in[8], (const float*)d_in[9], (const float*)d_in[10]};
    const float* bt[3] = {(const float*)d_in[11], (const float*)d_in[12], (const float*)d_in[13]};
    float* out = (float*)d_out;

    float* xbuf = nullptr;
    cudaGetSymbolAddress((void**)&xbuf, g_x);

    const int TB = 256;
    zero_deg_kernel<<<(NN + TB - 1) / TB, TB>>>();
    count_deg_kernel<<<(EE + TB - 1) / TB, TB>>>(ei);
    dinv_kernel<<<(NN + TB - 1) / TB, TB>>>();

    for (int i = 0; i < 3; i++) {
        if (i == 0)
            mm0_kernel<<<(NN + 511) / 512, 128>>>(x, W[0]);
        else
            mm16_kernel<<<(NN + TB - 1) / TB, TB>>>(xbuf, W[i]);

        zero_agg_kernel<<<(NN * HID + TB - 1) / TB, TB>>>();
        scatter_kernel<<<((unsigned)EE * 4u + TB - 1) / TB, TB>>>(ei);
        stats_kernel<<<(NN + 255) / 256, 256>>>(L[i]);
        finalize_kernel<<<1, GF>>>(gm[i], bt[i]);
        apply_kernel<<<(NN + 255) / 256, 256>>>(i == 2 ? out : xbuf);
    }
}

// round 2
// speedup vs baseline: 1.1338x; 1.1338x over previous
#include <cuda_runtime.h>
#include <math_constants.h>

#define NN   100000
#define EE   3200000
#define FIN  512
#define HID  16
#define NG   10
#define GF   160
#define LAMDA 0.001f
#define EPSN  1e-5f

#define SCAN_CHUNK 1024
#define NBLK ((NN + SCAN_CHUNK - 1) / SCAN_CHUNK)   // 98

// ---------------- device scratch ----------------
__device__ float  g_deg[NN];            // dinv
__device__ int    g_cnt[NN];            // in-degree (int)
__device__ int    g_rowstart[NN];       // CSR offsets (exclusive scan of cnt)
__device__ int    g_fill[NN];           // fill cursors
__device__ int    g_bsum[NBLK];         // scan block sums
__device__ int    g_csr_r[EE];          // CSR: source row per edge, grouped by col
__device__ float  g_h  [NN * HID];      // mm output (pre-scaled by dinv[row])
__device__ float  g_agg[NN * HID];      // gather output
__device__ float  g_x  [NN * HID];      // post-layer features
__device__ float  g_s  [NN * NG];       // softmax assignments
__device__ double g_sums[2 * GF];
__device__ float  g_rsg[GF];
__device__ float  g_cvec[HID];

// ---------------- init: zero counters ----------------
__global__ void zero_init_kernel() {
    int i = blockIdx.x * blockDim.x + threadIdx.x;
    if (i < NN) { g_cnt[i] = 0; g_fill[i] = 0; }
}

__global__ void count_kernel(const int* __restrict__ ei) {
    int e = blockIdx.x * blockDim.x + threadIdx.x;
    if (e < EE) atomicAdd(&g_cnt[__ldg(&ei[EE + e])], 1);
}

__global__ void dinv_kernel() {
    int i = blockIdx.x * blockDim.x + threadIdx.x;
    if (i < NN) {
        int d = g_cnt[i];
        g_deg[i] = (d > 0) ? rsqrtf((float)d) : 0.0f;
    }
}

// ---------------- prefix scan (3 kernels) ----------------
__global__ __launch_bounds__(512) void scan1_kernel() {
    __shared__ int sh[512];
    int b = blockIdx.x, t = threadIdx.x;
    int i0 = b * SCAN_CHUNK + 2 * t;
    int c0 = (i0     < NN) ? g_cnt[i0]     : 0;
    int c1 = (i0 + 1 < NN) ? g_cnt[i0 + 1] : 0;
    sh[t] = c0 + c1;
    __syncthreads();
    for (int off = 256; off > 0; off >>= 1) {
        if (t < off) sh[t] += sh[t + off];
        __syncthreads();
    }
    if (t == 0) g_bsum[b] = sh[0];
}

__global__ void scan2_kernel() {
    if (threadIdx.x == 0) {
        int acc = 0;
        for (int i = 0; i < NBLK; i++) { int v = g_bsum[i]; g_bsum[i] = acc; acc += v; }
    }
}

__global__ __launch_bounds__(512) void scan3_kernel() {
    __shared__ int sh[512];
    int b = blockIdx.x, t = threadIdx.x;
    int i0 = b * SCAN_CHUNK + 2 * t;
    int c0 = (i0     < NN) ? g_cnt[i0]     : 0;
    int c1 = (i0 + 1 < NN) ? g_cnt[i0 + 1] : 0;
    int pair = c0 + c1;
    sh[t] = pair;
    __syncthreads();
    // Hillis-Steele inclusive scan over 512
    for (int off = 1; off < 512; off <<= 1) {
        int v = (t >= off) ? sh[t - off] : 0;
        __syncthreads();
        sh[t] += v;
        __syncthreads();
    }
    int ex = sh[t] - pair + g_bsum[b];
    if (i0     < NN) g_rowstart[i0]     = ex;
    if (i0 + 1 < NN) g_rowstart[i0 + 1] = ex + c0;
}

__global__ void fill_kernel(const int* __restrict__ ei) {
    int e = blockIdx.x * blockDim.x + threadIdx.x;
    if (e >= EE) return;
    int r = __ldg(&ei[e]);
    int c = __ldg(&ei[EE + e]);
    int pos = g_rowstart[c] + atomicAdd(&g_fill[c], 1);
    g_csr_r[pos] = r;
}

// ---------------- mm0: [N,512]@[512,16], scaled by dinv[n] ----------------
__global__ __launch_bounds__(256) void mm0_kernel(const float* __restrict__ x,
                                                  const float* __restrict__ W) {
    __shared__ float Ws[FIN * HID];
    for (int i = threadIdx.x; i < FIN * HID; i += 256) Ws[i] = W[i];
    __syncthreads();

    int n = blockIdx.x * 256 + threadIdx.x;
    if (n >= NN) return;

    float acc[HID];
#pragma unroll
    for (int f = 0; f < HID; f++) acc[f] = 0.0f;

    const float4* x4 = (const float4*)(x + (size_t)n * FIN);
    for (int k8 = 0; k8 < FIN / 32; k8++) {
        float4 v[8];
#pragma unroll
        for (int j = 0; j < 8; j++) v[j] = x4[k8 * 8 + j];
#pragma unroll
        for (int j = 0; j < 8; j++) {
            float xk[4] = {v[j].x, v[j].y, v[j].z, v[j].w};
#pragma unroll
            for (int kk = 0; kk < 4; kk++) {
                int k = k8 * 32 + j * 4 + kk;
#pragma unroll
                for (int f = 0; f < HID; f++) acc[f] += xk[kk] * Ws[k * HID + f];
            }
        }
    }

    float dv = g_deg[n];
    float4* o = (float4*)&g_h[(size_t)n * HID];
#pragma unroll
    for (int q = 0; q < 4; q++)
        o[q] = make_float4(acc[q * 4 + 0] * dv, acc[q * 4 + 1] * dv,
                           acc[q * 4 + 2] * dv, acc[q * 4 + 3] * dv);
}

// ---------------- mm16: [N,16]@[16,16], scaled by dinv[n] ----------------
__global__ void mm16_kernel(const float* __restrict__ xin,
                            const float* __restrict__ W) {
    __shared__ float Ws[HID * HID];
    if (threadIdx.x < HID * HID) Ws[threadIdx.x] = W[threadIdx.x];
    __syncthreads();
    int n = blockIdx.x * blockDim.x + threadIdx.x;
    if (n >= NN) return;

    float xr[HID];
    const float4* xi = (const float4*)&xin[(size_t)n * HID];
#pragma unroll
    for (int q = 0; q < 4; q++) {
        float4 v = xi[q];
        xr[q * 4 + 0] = v.x; xr[q * 4 + 1] = v.y; xr[q * 4 + 2] = v.z; xr[q * 4 + 3] = v.w;
    }
    float acc[HID];
#pragma unroll
    for (int f = 0; f < HID; f++) acc[f] = 0.0f;
#pragma unroll
    for (int k = 0; k < HID; k++)
#pragma unroll
        for (int f = 0; f < HID; f++) acc[f] += xr[k] * Ws[k * HID + f];

    float dv = g_deg[n];
    float4* o = (float4*)&g_h[(size_t)n * HID];
#pragma unroll
    for (int q = 0; q < 4; q++)
        o[q] = make_float4(acc[q * 4 + 0] * dv, acc[q * 4 + 1] * dv,
                           acc[q * 4 + 2] * dv, acc[q * 4 + 3] * dv);
}

// ---------------- gather: warp per node, 4 lanes per edge ----------------
__global__ __launch_bounds__(256) void gather_kernel() {
    int node = blockIdx.x * 8 + (threadIdx.x >> 5);
    if (node >= NN) return;
    int lane = threadIdx.x & 31;
    int p = lane & 3;

    int s = g_rowstart[node];
    int e = s + g_cnt[node];

    float4 acc = make_float4(0.f, 0.f, 0.f, 0.f);
    for (int j = s + (lane >> 2); j < e; j += 8) {
        int r = g_csr_r[j];
        float4 v = ((const float4*)g_h)[(size_t)r * 4 + p];
        acc.x += v.x; acc.y += v.y; acc.z += v.z; acc.w += v.w;
    }
    // reduce across the 8 edge-groups (lanes with same p)
#pragma unroll
    for (int m = 16; m >= 4; m >>= 1) {
        acc.x += __shfl_xor_sync(0xffffffff, acc.x, m);
        acc.y += __shfl_xor_sync(0xffffffff, acc.y, m);
        acc.z += __shfl_xor_sync(0xffffffff, acc.z, m);
        acc.w += __shfl_xor_sync(0xffffffff, acc.w, m);
    }
    if (lane < 4) {
        float dc = g_deg[node];
        acc.x *= dc; acc.y *= dc; acc.z *= dc; acc.w *= dc;
        ((float4*)g_agg)[(size_t)node * 4 + lane] = acc;
    }
}

// ---------------- zero stat sums ----------------
__global__ void zero_sums_kernel() {
    int i = threadIdx.x;
    if (i < 2 * GF) g_sums[i] = 0.0;
}

// ---------------- stats: softmax + per-channel sums ----------------
__global__ __launch_bounds__(256) void stats_kernel(const float* __restrict__ L) {
    __shared__ float Ls[HID * NG];
    __shared__ float xs[256 * HID];
    __shared__ float ss[256 * NG];
    int tid = threadIdx.x;
    if (tid < HID * NG) Ls[tid] = L[tid];
    __syncthreads();

    int nIdx = blockIdx.x * 256 + tid;
    float xr[HID];
    float sv[NG];
#pragma unroll
    for (int k = 0; k < HID; k++) xr[k] = 0.0f;
#pragma unroll
    for (int g = 0; g < NG; g++) sv[g] = 0.0f;

    if (nIdx < NN) {
        const float4* xi = (const float4*)&g_agg[(size_t)nIdx * HID];
#pragma unroll
        for (int q = 0; q < 4; q++) {
            float4 v = xi[q];
            xr[q * 4 + 0] = v.x; xr[q * 4 + 1] = v.y; xr[q * 4 + 2] = v.z; xr[q * 4 + 3] = v.w;
        }
        float logit[NG];
#pragma unroll
        for (int g = 0; g < NG; g++) logit[g] = 0.0f;
#pragma unroll
        for (int k = 0; k < HID; k++)
#pragma unroll
            for (int g = 0; g < NG; g++) logit[g] += xr[k] * Ls[k * NG + g];
        float m = -CUDART_INF_F;
#pragma unroll
        for (int g = 0; g < NG; g++) m = fmaxf(m, logit[g]);
        float sum = 0.0f;
#pragma unroll
        for (int g = 0; g < NG; g++) { sv[g] = __expf(logit[g] - m); sum += sv[g]; }
        float inv = 1.0f / sum;
#pragma unroll
        for (int g = 0; g < NG; g++) sv[g] *= inv;
#pragma unroll
        for (int g = 0; g < NG; g++) g_s[(size_t)nIdx * NG + g] = sv[g];
    }

    {
        float4* xw = (float4*)&xs[tid * HID];
#pragma unroll
        for (int q = 0; q < 4; q++)
            xw[q] = make_float4(xr[q * 4 + 0], xr[q * 4 + 1], xr[q * 4 + 2], xr[q * 4 + 3]);
#pragma unroll
        for (int g = 0; g < NG; g++) ss[tid * NG + g] = sv[g];
    }
    __syncthreads();

    if (tid < GF) {
        int g = tid >> 4;
        int f = tid & 15;
        float a1 = 0.0f, a2 = 0.0f;
        for (int j = 0; j < 256; j++) {
            float t = ss[j * NG + g] * xs[j * HID + f];
            a1 += t;
            a2 += t * t;
        }
        atomicAdd(&g_sums[tid], (double)a1);
        atomicAdd(&g_sums[GF + tid], (double)a2);
    }
}

// ---------------- finalize BN constants ----------------
__global__ void finalize_kernel(const float* __restrict__ gamma,
                                const float* __restrict__ beta) {
    __shared__ float tsh[GF];
    int c = threadIdx.x;
    if (c < GF) {
        double mean = g_sums[c] / (double)NN;
        double var  = g_sums[GF + c] / (double)NN - mean * mean;
        float v = (float)var;
        if (v < 0.0f) v = 0.0f;
        float rs = rsqrtf(v + EPSN);
        float rg = rs * gamma[c];
        g_rsg[c] = rg;
        tsh[c] = beta[c] - (float)mean * rg;
    }
    __syncthreads();
    if (c < HID) {
        float cf = 0.0f;
#pragma unroll
        for (int g = 0; g < NG; g++) cf += tsh[g * HID + c];
        g_cvec[c] = cf;
    }
}

// ---------------- apply: x + lambda*(x*a + c), relu ----------------
__global__ __launch_bounds__(256) void apply_kernel(float* __restrict__ out) {
    __shared__ float rg[GF];
    __shared__ float cs[HID];
    int tid = threadIdx.x;
    if (tid < GF) rg[tid] = g_rsg[tid];
    if (tid < HID) cs[tid] = g_cvec[tid];
    __syncthreads();

    int nIdx = blockIdx.x * 256 + tid;
    if (nIdx >= NN) return;

    float sv[NG];
#pragma unroll
    for (int g = 0; g < NG; g++) sv[g] = g_s[(size_t)nIdx * NG + g];

    float xr[HID];
    const float4* xi = (const float4*)&g_agg[(size_t)nIdx * HID];
#pragma unroll
    for (int q = 0; q < 4; q++) {
        float4 v = xi[q];
        xr[q * 4 + 0] = v.x; xr[q * 4 + 1] = v.y; xr[q * 4 + 2] = v.z; xr[q * 4 + 3] = v.w;
    }

    float res[HID];
#pragma unroll
    for (int f = 0; f < HID; f++) {
        float a = 0.0f;
#pragma unroll
        for (int g = 0; g < NG; g++) a += sv[g] * rg[g * HID + f];
        float v = xr[f] + LAMDA * (xr[f] * a + cs[f]);
        res[f] = fmaxf(v, 0.0f);
    }

    float4* o = (float4*)&out[(size_t)nIdx * HID];
#pragma unroll
    for (int q = 0; q < 4; q++)
        o[q] = make_float4(res[q * 4 + 0], res[q * 4 + 1], res[q * 4 + 2], res[q * 4 + 3]);
}

// ---------------- launcher ----------------
extern "C" void kernel_launch(void* const* d_in, const int* in_sizes, int n_in,
                              void* d_out, int out_size) {
    const float* x  = (const float*)d_in[0];
    const int*   ei = (const int*)d_in[1];
    const float* W[3] = {(const float*)d_in[2], (const float*)d_in[3], (const float*)d_in[4]};
    const float* L[3] = {(const float*)d_in[5], (const float*)d_in[6], (const float*)d_in[7]};
    const float* gm[3] = {(const float*)d_in[8], (const float*)d_in[9], (const float*)d_in[10]};
    const float* bt[3] = {(const float*)d_in[11], (const float*)d_in[12], (const float*)d_in[13]};
    float* out = (float*)d_out;

    float* xbuf = nullptr;
    cudaGetSymbolAddress((void**)&xbuf, g_x);

    const int TB = 256;
    zero_init_kernel<<<(NN + TB - 1) / TB, TB>>>();
    count_kernel<<<(EE + TB - 1) / TB, TB>>>(ei);
    scan1_kernel<<<NBLK, 512>>>();
    scan2_kernel<<<1, 32>>>();
    scan3_kernel<<<NBLK, 512>>>();
    dinv_kernel<<<(NN + TB - 1) / TB, TB>>>();
    fill_kernel<<<(EE + TB - 1) / TB, TB>>>(ei);

    for (int i = 0; i < 3; i++) {
        if (i == 0)
            mm0_kernel<<<(NN + 255) / 256, 256>>>(x, W[0]);
        else
            mm16_kernel<<<(NN + TB - 1) / TB, TB>>>(xbuf, W[i]);

        gather_kernel<<<(NN + 7) / 8, 256>>>();
        zero_sums_kernel<<<1, 2 * GF>>>();
        stats_kernel<<<(NN + 255) / 256, 256>>>(L[i]);
        finalize_kernel<<<1, GF>>>(gm[i], bt[i]);
        apply_kernel<<<(NN + 255) / 256, 256>>>(i == 2 ? out : xbuf);
    }
}

// round 3
// speedup vs baseline: 1.2424x; 1.0957x over previous
#include <cuda_runtime.h>
#include <math_constants.h>

#define NN   100000
#define EE   3200000
#define FIN  512
#define HID  16
#define NG   10
#define GF   160
#define LAMDA 0.001f
#define EPSN  1e-5f

#define SCAN_CHUNK 1024
#define NBLK ((NN + SCAN_CHUNK - 1) / SCAN_CHUNK)   // 98

// ---------------- device scratch ----------------
__device__ float  g_deg[NN];            // dinv
__device__ int    g_cnt[NN];            // in-degree
__device__ int    g_rowstart[NN];       // CSR offsets
__device__ int    g_fill[NN];           // fill cursors (init = rowstart)
__device__ int    g_bsum[NBLK];
__device__ int    g_csr_r[EE];          // CSR: source row per edge, grouped by col
__device__ float  g_h  [NN * HID];      // mm output (pre-scaled by dinv[row])
__device__ float  g_agg[NN * HID];      // gather output
__device__ float  g_s  [NN * NG];       // softmax assignments
__device__ double g_sums[2 * GF];       // zero-init at load; finalize re-zeroes
__device__ float  g_rsg[GF];
__device__ float  g_cvec[HID];

// ---------------- helpers: packed f32x2 ----------------
__device__ __forceinline__ unsigned long long pack2(float a) {
    unsigned int u = __float_as_uint(a);
    unsigned long long r;
    asm("mov.b64 %0, {%1, %1};" : "=l"(r) : "r"(u));
    return r;
}
__device__ __forceinline__ void fma2(unsigned long long& acc,
                                     unsigned long long a, unsigned long long b) {
    asm("fma.rn.f32x2 %0, %1, %2, %3;" : "=l"(acc) : "l"(a), "l"(b), "l"(acc));
}

// ---------------- CSR build ----------------
__global__ void zero_cnt_kernel() {
    int i = blockIdx.x * blockDim.x + threadIdx.x;
    if (i < NN) g_cnt[i] = 0;
}

__global__ void count_kernel(const int* __restrict__ ei) {
    int e = blockIdx.x * blockDim.x + threadIdx.x;
    if (e < EE) atomicAdd(&g_cnt[__ldg(&ei[EE + e])], 1);
}

__global__ __launch_bounds__(512) void scan1_kernel() {
    __shared__ int sh[512];
    int b = blockIdx.x, t = threadIdx.x;
    int i0 = b * SCAN_CHUNK + 2 * t;
    int c0 = (i0     < NN) ? g_cnt[i0]     : 0;
    int c1 = (i0 + 1 < NN) ? g_cnt[i0 + 1] : 0;
    sh[t] = c0 + c1;
    __syncthreads();
    for (int off = 256; off > 0; off >>= 1) {
        if (t < off) sh[t] += sh[t + off];
        __syncthreads();
    }
    if (t == 0) g_bsum[b] = sh[0];
}

// parallel exclusive scan of NBLK (=98) block sums, one block of 128
__global__ __launch_bounds__(128) void scan2_kernel() {
    __shared__ int sh[128];
    int t = threadIdx.x;
    int v = (t < NBLK) ? g_bsum[t] : 0;
    sh[t] = v;
    __syncthreads();
    for (int off = 1; off < 128; off <<= 1) {
        int u = (t >= off) ? sh[t - off] : 0;
        __syncthreads();
        sh[t] += u;
        __syncthreads();
    }
    if (t < NBLK) g_bsum[t] = sh[t] - v;   // exclusive
}

__global__ __launch_bounds__(512) void scan3_kernel() {
    __shared__ int sh[512];
    int b = blockIdx.x, t = threadIdx.x;
    int i0 = b * SCAN_CHUNK + 2 * t;
    int c0 = (i0     < NN) ? g_cnt[i0]     : 0;
    int c1 = (i0 + 1 < NN) ? g_cnt[i0 + 1] : 0;
    int pair = c0 + c1;
    sh[t] = pair;
    __syncthreads();
    for (int off = 1; off < 512; off <<= 1) {
        int v = (t >= off) ? sh[t - off] : 0;
        __syncthreads();
        sh[t] += v;
        __syncthreads();
    }
    int ex = sh[t] - pair + g_bsum[b];
    if (i0 < NN) {
        g_rowstart[i0] = ex;
        g_fill[i0] = ex;
        g_deg[i0] = (c0 > 0) ? rsqrtf((float)c0) : 0.0f;
    }
    if (i0 + 1 < NN) {
        g_rowstart[i0 + 1] = ex + c0;
        g_fill[i0 + 1] = ex + c0;
        g_deg[i0 + 1] = (c1 > 0) ? rsqrtf((float)c1) : 0.0f;
    }
}

__global__ void fill_kernel(const int* __restrict__ ei) {
    int e = blockIdx.x * blockDim.x + threadIdx.x;
    if (e >= EE) return;
    int r = __ldg(&ei[e]);
    int c = __ldg(&ei[EE + e]);
    int pos = atomicAdd(&g_fill[c], 1);
    g_csr_r[pos] = r;
}

// ---------------- mm0: [N,512]@[512,16], scaled by dinv[n], packed f32x2 ----------------
__global__ __launch_bounds__(256) void mm0_kernel(const float* __restrict__ x,
                                                  const float* __restrict__ W) {
    __shared__ __align__(16) float Ws[FIN * HID];
    for (int i = threadIdx.x; i < FIN * HID; i += 256) Ws[i] = W[i];
    __syncthreads();

    int n = blockIdx.x * 256 + threadIdx.x;
    if (n >= NN) return;

    unsigned long long acc2[8];
#pragma unroll
    for (int p = 0; p < 8; p++) acc2[p] = 0ull;

    const float4* x4 = (const float4*)(x + (size_t)n * FIN);
    for (int k8 = 0; k8 < FIN / 32; k8++) {
        float4 v[8];
#pragma unroll
        for (int j = 0; j < 8; j++) v[j] = x4[k8 * 8 + j];
#pragma unroll
        for (int j = 0; j < 8; j++) {
            float xk[4] = {v[j].x, v[j].y, v[j].z, v[j].w};
#pragma unroll
            for (int kk = 0; kk < 4; kk++) {
                int k = k8 * 32 + j * 4 + kk;
                const ulonglong2* wp = (const ulonglong2*)&Ws[k * HID];
                unsigned long long xp = pack2(xk[kk]);
                ulonglong2 w01 = wp[0], w23 = wp[1], w45 = wp[2], w67 = wp[3];
                fma2(acc2[0], xp, w01.x); fma2(acc2[1], xp, w01.y);
                fma2(acc2[2], xp, w23.x); fma2(acc2[3], xp, w23.y);
                fma2(acc2[4], xp, w45.x); fma2(acc2[5], xp, w45.y);
                fma2(acc2[6], xp, w67.x); fma2(acc2[7], xp, w67.y);
            }
        }
    }

    float dv = g_deg[n];
    union { unsigned long long u; float2 f; } cv;
    float4* o = (float4*)&g_h[(size_t)n * HID];
#pragma unroll
    for (int q = 0; q < 4; q++) {
        float4 r;
        cv.u = acc2[2 * q];     r.x = cv.f.x * dv; r.y = cv.f.y * dv;
        cv.u = acc2[2 * q + 1]; r.z = cv.f.x * dv; r.w = cv.f.y * dv;
        o[q] = r;
    }
}

// ---------------- gather: warp per node, 4 lanes per edge, 2-way unrolled ----------------
__global__ __launch_bounds__(256) void gather_kernel() {
    int node = blockIdx.x * 8 + (threadIdx.x >> 5);
    if (node >= NN) return;
    int lane = threadIdx.x & 31;
    int p = lane & 3;

    int s = g_rowstart[node];
    int e = s + g_cnt[node];
    int j = s + (lane >> 2);

    float4 a0 = make_float4(0.f, 0.f, 0.f, 0.f);
    float4 a1 = make_float4(0.f, 0.f, 0.f, 0.f);
    const float4* h4 = (const float4*)g_h;

    while (j < e - 8) {
        int r0 = __ldg(&g_csr_r[j]);
        int r1 = __ldg(&g_csr_r[j + 8]);
        float4 v0 = __ldg(&h4[(size_t)r0 * 4 + p]);
        float4 v1 = __ldg(&h4[(size_t)r1 * 4 + p]);
        a0.x += v0.x; a0.y += v0.y; a0.z += v0.z; a0.w += v0.w;
        a1.x += v1.x; a1.y += v1.y; a1.z += v1.z; a1.w += v1.w;
        j += 16;
    }
    if (j < e) {
        int r0 = __ldg(&g_csr_r[j]);
        float4 v0 = __ldg(&h4[(size_t)r0 * 4 + p]);
        a0.x += v0.x; a0.y += v0.y; a0.z += v0.z; a0.w += v0.w;
    }
    a0.x += a1.x; a0.y += a1.y; a0.z += a1.z; a0.w += a1.w;

#pragma unroll
    for (int m = 16; m >= 4; m >>= 1) {
        a0.x += __shfl_xor_sync(0xffffffff, a0.x, m);
        a0.y += __shfl_xor_sync(0xffffffff, a0.y, m);
        a0.z += __shfl_xor_sync(0xffffffff, a0.z, m);
        a0.w += __shfl_xor_sync(0xffffffff, a0.w, m);
    }
    if (lane < 4) {
        float dc = g_deg[node];
        a0.x *= dc; a0.y *= dc; a0.z *= dc; a0.w *= dc;
        ((float4*)g_agg)[(size_t)node * 4 + lane] = a0;
    }
}

// ---------------- stats: softmax + per-channel sums ----------------
__global__ __launch_bounds__(256) void stats_kernel(const float* __restrict__ L) {
    __shared__ float Ls[HID * NG];
    __shared__ float xs[256 * HID];
    __shared__ float ss[256 * NG];
    int tid = threadIdx.x;
    if (tid < HID * NG) Ls[tid] = L[tid];
    __syncthreads();

    int nIdx = blockIdx.x * 256 + tid;
    float xr[HID];
    float sv[NG];
#pragma unroll
    for (int k = 0; k < HID; k++) xr[k] = 0.0f;
#pragma unroll
    for (int g = 0; g < NG; g++) sv[g] = 0.0f;

    if (nIdx < NN) {
        const float4* xi = (const float4*)&g_agg[(size_t)nIdx * HID];
#pragma unroll
        for (int q = 0; q < 4; q++) {
            float4 v = xi[q];
            xr[q * 4 + 0] = v.x; xr[q * 4 + 1] = v.y; xr[q * 4 + 2] = v.z; xr[q * 4 + 3] = v.w;
        }
        float logit[NG];
#pragma unroll
        for (int g = 0; g < NG; g++) logit[g] = 0.0f;
#pragma unroll
        for (int k = 0; k < HID; k++)
#pragma unroll
            for (int g = 0; g < NG; g++) logit[g] += xr[k] * Ls[k * NG + g];
        float m = -CUDART_INF_F;
#pragma unroll
        for (int g = 0; g < NG; g++) m = fmaxf(m, logit[g]);
        float sum = 0.0f;
#pragma unroll
        for (int g = 0; g < NG; g++) { sv[g] = __expf(logit[g] - m); sum += sv[g]; }
        float inv = 1.0f / sum;
#pragma unroll
        for (int g = 0; g < NG; g++) sv[g] *= inv;
#pragma unroll
        for (int g = 0; g < NG; g++) g_s[(size_t)nIdx * NG + g] = sv[g];
    }

    {
        float4* xw = (float4*)&xs[tid * HID];
#pragma unroll
        for (int q = 0; q < 4; q++)
            xw[q] = make_float4(xr[q * 4 + 0], xr[q * 4 + 1], xr[q * 4 + 2], xr[q * 4 + 3]);
#pragma unroll
        for (int g = 0; g < NG; g++) ss[tid * NG + g] = sv[g];
    }
    __syncthreads();

    if (tid < GF) {
        int g = tid >> 4;
        int f = tid & 15;
        float a1 = 0.0f, a2 = 0.0f;
        for (int jj = 0; jj < 256; jj++) {
            float t = ss[jj * NG + g] * xs[jj * HID + f];
            a1 += t;
            a2 += t * t;
        }
        atomicAdd(&g_sums[tid], (double)a1);
        atomicAdd(&g_sums[GF + tid], (double)a2);
    }
}

// ---------------- finalize BN constants (self-zeroing) ----------------
__global__ void finalize_kernel(const float* __restrict__ gamma,
                                const float* __restrict__ beta) {
    __shared__ float tsh[GF];
    int c = threadIdx.x;
    if (c < GF) {
        double s1 = g_sums[c];
        double s2 = g_sums[GF + c];
        g_sums[c] = 0.0;           // re-zero for next layer / next replay
        g_sums[GF + c] = 0.0;
        double mean = s1 / (double)NN;
        double var  = s2 / (double)NN - mean * mean;
        float v = (float)var;
        if (v < 0.0f) v = 0.0f;
        float rs = rsqrtf(v + EPSN);
        float rg = rs * gamma[c];
        g_rsg[c] = rg;
        tsh[c] = beta[c] - (float)mean * rg;
    }
    __syncthreads();
    if (c < HID) {
        float cf = 0.0f;
#pragma unroll
        for (int g = 0; g < NG; g++) cf += tsh[g * HID + c];
        g_cvec[c] = cf;
    }
}

// ---------------- apply + fused next-layer mm16 -> g_h (pre-scaled) ----------------
__global__ __launch_bounds__(256) void apply_mm_kernel(const float* __restrict__ Wn) {
    __shared__ float rg[GF];
    __shared__ float cs[HID];
    __shared__ float Ws[HID * HID];
    int tid = threadIdx.x;
    if (tid < GF) rg[tid] = g_rsg[tid];
    if (tid < HID) cs[tid] = g_cvec[tid];
    if (tid < HID * HID) Ws[tid] = Wn[tid];
    __syncthreads();

    int nIdx = blockIdx.x * 256 + tid;
    if (nIdx >= NN) return;

    float sv[NG];
#pragma unroll
    for (int g = 0; g < NG; g++) sv[g] = g_s[(size_t)nIdx * NG + g];

    float xr[HID];
    const float4* xi = (const float4*)&g_agg[(size_t)nIdx * HID];
#pragma unroll
    for (int q = 0; q < 4; q++) {
        float4 v = xi[q];
        xr[q * 4 + 0] = v.x; xr[q * 4 + 1] = v.y; xr[q * 4 + 2] = v.z; xr[q * 4 + 3] = v.w;
    }

    float res[HID];
#pragma unroll
    for (int f = 0; f < HID; f++) {
        float a = 0.0f;
#pragma unroll
        for (int g = 0; g < NG; g++) a += sv[g] * rg[g * HID + f];
        float v = xr[f] + LAMDA * (xr[f] * a + cs[f]);
        res[f] = fmaxf(v, 0.0f);
    }

    // fused mm16: h = (res @ Wn) * dinv[n]
    float acc[HID];
#pragma unroll
    for (int f = 0; f < HID; f++) acc[f] = 0.0f;
#pragma unroll
    for (int k = 0; k < HID; k++)
#pragma unroll
        for (int f = 0; f < HID; f++) acc[f] += res[k] * Ws[k * HID + f];

    float dv = g_deg[nIdx];
    float4* o = (float4*)&g_h[(size_t)nIdx * HID];
#pragma unroll
    for (int q = 0; q < 4; q++)
        o[q] = make_float4(acc[q * 4 + 0] * dv, acc[q * 4 + 1] * dv,
                           acc[q * 4 + 2] * dv, acc[q * 4 + 3] * dv);
}

// ---------------- final apply (layer 2): write output ----------------
__global__ __launch_bounds__(256) void apply_out_kernel(float* __restrict__ out) {
    __shared__ float rg[GF];
    __shared__ float cs[HID];
    int tid = threadIdx.x;
    if (tid < GF) rg[tid] = g_rsg[tid];
    if (tid < HID) cs[tid] = g_cvec[tid];
    __syncthreads();

    int nIdx = blockIdx.x * 256 + tid;
    if (nIdx >= NN) return;

    float sv[NG];
#pragma unroll
    for (int g = 0; g < NG; g++) sv[g] = g_s[(size_t)nIdx * NG + g];

    float xr[HID];
    const float4* xi = (const float4*)&g_agg[(size_t)nIdx * HID];
#pragma unroll
    for (int q = 0; q < 4; q++) {
        float4 v = xi[q];
        xr[q * 4 + 0] = v.x; xr[q * 4 + 1] = v.y; xr[q * 4 + 2] = v.z; xr[q * 4 + 3] = v.w;
    }

    float res[HID];
#pragma unroll
    for (int f = 0; f < HID; f++) {
        float a = 0.0f;
#pragma unroll
        for (int g = 0; g < NG; g++) a += sv[g] * rg[g * HID + f];
        float v = xr[f] + LAMDA * (xr[f] * a + cs[f]);
        res[f] = fmaxf(v, 0.0f);
    }

    float4* o = (float4*)&out[(size_t)nIdx * HID];
#pragma unroll
    for (int q = 0; q < 4; q++)
        o[q] = make_float4(res[q * 4 + 0], res[q * 4 + 1], res[q * 4 + 2], res[q * 4 + 3]);
}

// ---------------- launcher ----------------
extern "C" void kernel_launch(void* const* d_in, const int* in_sizes, int n_in,
                              void* d_out, int out_size) {
    const float* x  = (const float*)d_in[0];
    const int*   ei = (const int*)d_in[1];
    const float* W[3] = {(const float*)d_in[2], (const float*)d_in[3], (const float*)d_in[4]};
    const float* L[3] = {(const float*)d_in[5], (const float*)d_in[6], (const float*)d_in[7]};
    const float* gm[3] = {(const float*)d_in[8], (const float*)d_in[9], (const float*)d_in[10]};
    const float* bt[3] = {(const float*)d_in[11], (const float*)d_in[12], (const float*)d_in[13]};
    float* out = (float*)d_out;

    const int TB = 256;
    zero_cnt_kernel<<<(NN + TB - 1) / TB, TB>>>();
    count_kernel<<<(EE + TB - 1) / TB, TB>>>(ei);
    scan1_kernel<<<NBLK, 512>>>();
    scan2_kernel<<<1, 128>>>();
    scan3_kernel<<<NBLK, 512>>>();
    fill_kernel<<<(EE + TB - 1) / TB, TB>>>(ei);

    mm0_kernel<<<(NN + 255) / 256, 256>>>(x, W[0]);

    for (int i = 0; i < 3; i++) {
        gather_kernel<<<(NN + 7) / 8, 256>>>();
        stats_kernel<<<(NN + 255) / 256, 256>>>(L[i]);
        finalize_kernel<<<1, GF>>>(gm[i], bt[i]);
        if (i < 2)
            apply_mm_kernel<<<(NN + 255) / 256, 256>>>(W[i + 1]);
        else
            apply_out_kernel<<<(NN + 255) / 256, 256>>>(out);
    }
}